// round 2
// baseline (speedup 1.0000x reference)
#include <cuda_runtime.h>
#include <cuda_bf16.h>

#define MAXN 100000
#define MAXE 600000
#define NG_GRAPHS 512

// Scratch (static device globals; allocation-free).
__device__ __align__(16) float g_t[MAXN * 128];
__device__ __align__(16) float g_acc[MAXN * 128];
__device__ __align__(16) float g_h[MAXN * 128];
__device__ __align__(16) float g_deg[MAXN];
__device__ __align__(16) float g_dis[MAXN];
__device__ __align__(16) float g_sums[NG_GRAPHS * 64];
__device__ __align__(16) float g_cnt[NG_GRAPHS];

// ---------------------------------------------------------------------------
// degree / normalization
// ---------------------------------------------------------------------------
__global__ void init_deg_kernel(float* deg, int N) {
    int i = blockIdx.x * blockDim.x + threadIdx.x;
    if (i < N) deg[i] = 1.0f;  // self-loop
}

__global__ void count_deg_kernel(const int* __restrict__ dst, float* deg, int E) {
    int i = blockIdx.x * blockDim.x + threadIdx.x;
    if (i < E) atomicAdd(&deg[dst[i]], 1.0f);
}

__global__ void make_dis_kernel(const float* __restrict__ deg, float* dis, int N) {
    int i = blockIdx.x * blockDim.x + threadIdx.x;
    if (i < N) dis[i] = rsqrtf(deg[i]);
}

// ---------------------------------------------------------------------------
// layer 1: t[n] = (x[n] @ W1) * dis[n],  K=3, F=128
// ---------------------------------------------------------------------------
__global__ __launch_bounds__(256) void layer1_kernel(
    const float* __restrict__ x, const float* __restrict__ W1,
    const float* __restrict__ dis, float* __restrict__ t, int N) {
    __shared__ float ws[3 * 128];
    for (int i = threadIdx.x; i < 384; i += blockDim.x) ws[i] = W1[i];
    __syncthreads();
    int idx = blockIdx.x * blockDim.x + threadIdx.x;
    int n = idx >> 5;
    int l = idx & 31;
    if (n >= N) return;
    float x0 = x[n * 3 + 0], x1 = x[n * 3 + 1], x2 = x[n * 3 + 2];
    float d = dis[n];
    int f = l * 4;
    float4 o;
    o.x = (x0 * ws[f + 0] + x1 * ws[128 + f + 0] + x2 * ws[256 + f + 0]) * d;
    o.y = (x0 * ws[f + 1] + x1 * ws[128 + f + 1] + x2 * ws[256 + f + 1]) * d;
    o.z = (x0 * ws[f + 2] + x1 * ws[128 + f + 2] + x2 * ws[256 + f + 2]) * d;
    o.w = (x0 * ws[f + 3] + x1 * ws[128 + f + 3] + x2 * ws[256 + f + 3]) * d;
    *(float4*)(t + (size_t)n * 128 + f) = o;
}

// ---------------------------------------------------------------------------
// GEMM: out[n] = (A[n] @ W) * dis[n].  K=128 fixed, F in {64,128}.
// Tile: 64 nodes x F feats per block, 256 threads, 16-wide K chunks.
// ---------------------------------------------------------------------------
template <int F>
__global__ __launch_bounds__(256) void gemm_kernel(
    const float* __restrict__ A, const float* __restrict__ W,
    const float* __restrict__ dis, float* __restrict__ out, int N) {
    constexpr int K = 128, TN = 64, KC = 16;
    constexpr int FG = F / 4;        // float4 groups across feats
    constexpr int NG = 256 / FG;     // node groups
    constexpr int RN = TN / NG;      // rows per thread
    __shared__ float xs[TN][KC];
    __shared__ float ws[KC][F];

    const int tid = threadIdx.x;
    const int n0 = blockIdx.x * TN;
    const int fg = tid % FG;
    const int ng = tid / FG;

    float acc[RN][4];
#pragma unroll
    for (int i = 0; i < RN; i++) {
        acc[i][0] = acc[i][1] = acc[i][2] = acc[i][3] = 0.f;
    }

    for (int k0 = 0; k0 < K; k0 += KC) {
        // load xs: 64 x 16 floats = 256 float4, one per thread
        {
            int r = tid >> 2;
            int c = tid & 3;
            float4 xv = make_float4(0.f, 0.f, 0.f, 0.f);
            int n = n0 + r;
            if (n < N) xv = *(const float4*)(A + (size_t)n * K + k0 + c * 4);
            *(float4*)&xs[r][c * 4] = xv;
        }
        // load ws: KC x F floats
#pragma unroll
        for (int i = tid; i < KC * F / 4; i += 256) {
            int rr = i / (F / 4), cc = i % (F / 4);
            *(float4*)&ws[rr][cc * 4] = *(const float4*)(W + (size_t)(k0 + rr) * F + cc * 4);
        }
        __syncthreads();
#pragma unroll
        for (int kk = 0; kk < KC; kk++) {
            float4 wv = *(float4*)&ws[kk][fg * 4];
#pragma unroll
            for (int i = 0; i < RN; i++) {
                float xv = xs[ng * RN + i][kk];
                acc[i][0] = fmaf(xv, wv.x, acc[i][0]);
                acc[i][1] = fmaf(xv, wv.y, acc[i][1]);
                acc[i][2] = fmaf(xv, wv.z, acc[i][2]);
                acc[i][3] = fmaf(xv, wv.w, acc[i][3]);
            }
        }
        __syncthreads();
    }
#pragma unroll
    for (int i = 0; i < RN; i++) {
        int n = n0 + ng * RN + i;
        if (n < N) {
            float d = dis[n];
            float4 o = make_float4(acc[i][0] * d, acc[i][1] * d, acc[i][2] * d, acc[i][3] * d);
            *(float4*)(out + (size_t)n * F + fg * 4) = o;
        }
    }
}

// ---------------------------------------------------------------------------
// edge aggregation: acc[dst] += t[src]  (vectorized global float4 reduction)
// ---------------------------------------------------------------------------
template <int F>
__global__ __launch_bounds__(256) void aggregate_kernel(
    const int* __restrict__ src, const int* __restrict__ dst,
    const float* __restrict__ t, float* __restrict__ acc, int E) {
    constexpr int L = F / 4;
    int idx = blockIdx.x * blockDim.x + threadIdx.x;
    if (idx >= E * L) return;
    int e = idx / L;
    int l = idx - e * L;
    int s = src[e];
    int d = dst[e];
    float4 v = *(const float4*)(t + (size_t)s * F + l * 4);
    float* p = acc + (size_t)d * F + l * 4;
    asm volatile("red.global.add.v4.f32 [%0], {%1, %2, %3, %4};"
                 :: "l"(p), "f"(v.x), "f"(v.y), "f"(v.z), "f"(v.w)
                 : "memory");
}

// ---------------------------------------------------------------------------
// epilogue: h[n] = relu((acc[n] + t[n]) * dis[n] + b)   (self-loop = t[n])
// ---------------------------------------------------------------------------
template <int F>
__global__ __launch_bounds__(256) void act_kernel(
    const float* __restrict__ acc, const float* __restrict__ t,
    const float* __restrict__ dis, const float* __restrict__ b,
    float* __restrict__ h, int N) {
    constexpr int L = F / 4;
    int idx = blockIdx.x * blockDim.x + threadIdx.x;
    if (idx >= N * L) return;
    int n = idx / L;
    int l = idx - n * L;
    float d = dis[n];
    float4 a  = *(const float4*)(acc + (size_t)n * F + l * 4);
    float4 tv = *(const float4*)(t + (size_t)n * F + l * 4);
    float4 bv = *(const float4*)(b + l * 4);
    float4 o;
    o.x = fmaxf(fmaf(a.x + tv.x, d, bv.x), 0.f);
    o.y = fmaxf(fmaf(a.y + tv.y, d, bv.y), 0.f);
    o.z = fmaxf(fmaf(a.z + tv.z, d, bv.z), 0.f);
    o.w = fmaxf(fmaf(a.w + tv.w, d, bv.w), 0.f);
    *(float4*)(h + (size_t)n * F + l * 4) = o;
}

// ---------------------------------------------------------------------------
// pooling: batch is sorted -> segmented reduction, one atomic flush per
// (graph boundary, block). Block = 64 threads (one per feature), 256 nodes.
// ---------------------------------------------------------------------------
__global__ __launch_bounds__(64) void pool_kernel(
    const float* __restrict__ h, const int* __restrict__ batch,
    float* __restrict__ sums, float* __restrict__ cnt, int N) {
    int start = blockIdx.x * 256;
    int end = min(start + 256, N);
    int f = threadIdx.x;
    int g = batch[start];
    float s = 0.f, c = 0.f;
    for (int n = start; n < end; n++) {
        int bn = batch[n];
        if (bn != g) {
            atomicAdd(&sums[g * 64 + f], s);
            if (f == 0) atomicAdd(&cnt[g], c);
            s = 0.f; c = 0.f; g = bn;
        }
        s += h[(size_t)n * 64 + f];
        c += 1.f;
    }
    atomicAdd(&sums[g * 64 + f], s);
    if (f == 0) atomicAdd(&cnt[g], c);
}

// ---------------------------------------------------------------------------
// final: out[g] = (sums[g] / max(cnt,1)) . Wl + bl
// ---------------------------------------------------------------------------
__global__ void final_kernel(const float* __restrict__ sums, const float* __restrict__ cnt,
                             const float* __restrict__ Wl, const float* __restrict__ bl,
                             float* __restrict__ out) {
    int g = blockIdx.x * blockDim.x + threadIdx.x;
    if (g >= NG_GRAPHS) return;
    float c = fmaxf(cnt[g], 1.0f);
    float acc = 0.f;
#pragma unroll
    for (int f = 0; f < 64; f++) acc = fmaf(sums[g * 64 + f], Wl[f], acc);
    out[g] = acc / c + bl[0];
}

// ---------------------------------------------------------------------------
extern "C" void kernel_launch(void* const* d_in, const int* in_sizes, int n_in,
                              void* d_out, int out_size) {
    const float* x     = (const float*)d_in[0];
    const int*   ei    = (const int*)d_in[1];    // int32 (JAX default, no x64)
    const int*   batch = (const int*)d_in[2];    // int32
    const float* W1 = (const float*)d_in[3];
    const float* b1 = (const float*)d_in[4];
    const float* W2 = (const float*)d_in[5];
    const float* b2 = (const float*)d_in[6];
    const float* W3 = (const float*)d_in[7];
    const float* b3 = (const float*)d_in[8];
    const float* Wl = (const float*)d_in[9];
    const float* bl = (const float*)d_in[10];
    float* out = (float*)d_out;

    const int N = in_sizes[0] / 3;
    const int E = in_sizes[1] / 2;
    const int* srcp = ei;
    const int* dstp = ei + E;

    float *t, *acc, *h, *deg, *dis, *sums, *cnt;
    cudaGetSymbolAddress((void**)&t, g_t);
    cudaGetSymbolAddress((void**)&acc, g_acc);
    cudaGetSymbolAddress((void**)&h, g_h);
    cudaGetSymbolAddress((void**)&deg, g_deg);
    cudaGetSymbolAddress((void**)&dis, g_dis);
    cudaGetSymbolAddress((void**)&sums, g_sums);
    cudaGetSymbolAddress((void**)&cnt, g_cnt);

    const int nB = (N + 255) / 256;
    const int eB = (E + 255) / 256;
    const int nf128 = (N * 32 + 255) / 256;
    const int nf64 = (N * 16 + 255) / 256;
    const int ef128 = (E * 32 + 255) / 256;
    const int ef64 = (E * 16 + 255) / 256;
    const int gB = (N + 63) / 64;

    // degree + normalization
    init_deg_kernel<<<nB, 256>>>(deg, N);
    count_deg_kernel<<<eB, 256>>>(dstp, deg, E);
    make_dis_kernel<<<nB, 256>>>(deg, dis, N);

    // layer 1 (3 -> 128)
    layer1_kernel<<<nf128, 256>>>(x, W1, dis, t, N);
    cudaMemsetAsync(acc, 0, (size_t)N * 128 * sizeof(float), 0);
    aggregate_kernel<128><<<ef128, 256>>>(srcp, dstp, t, acc, E);
    act_kernel<128><<<nf128, 256>>>(acc, t, dis, b1, h, N);

    // layer 2 (128 -> 128)
    gemm_kernel<128><<<gB, 256>>>(h, W2, dis, t, N);
    cudaMemsetAsync(acc, 0, (size_t)N * 128 * sizeof(float), 0);
    aggregate_kernel<128><<<ef128, 256>>>(srcp, dstp, t, acc, E);
    act_kernel<128><<<nf128, 256>>>(acc, t, dis, b2, h, N);

    // layer 3 (128 -> 64)
    gemm_kernel<64><<<gB, 256>>>(h, W3, dis, t, N);
    cudaMemsetAsync(acc, 0, (size_t)N * 64 * sizeof(float), 0);
    aggregate_kernel<64><<<ef64, 256>>>(srcp, dstp, t, acc, E);
    act_kernel<64><<<nf64, 256>>>(acc, t, dis, b3, h, N);

    // pooling + final linear
    cudaMemsetAsync(sums, 0, NG_GRAPHS * 64 * sizeof(float), 0);
    cudaMemsetAsync(cnt, 0, NG_GRAPHS * sizeof(float), 0);
    pool_kernel<<<(N + 255) / 256, 64>>>(h, batch, sums, cnt, N);
    final_kernel<<<2, 256>>>(sums, cnt, Wl, bl, out);
}

// round 3
// speedup vs baseline: 1.3276x; 1.3276x over previous
#include <cuda_runtime.h>
#include <cuda_bf16.h>

#define MAXN 100000
#define MAXE 600000
#define NG_GRAPHS 512
#define SCAN_B 1024

// Scratch (static device globals; allocation-free).
__device__ __align__(16) float g_t[MAXN * 128];
__device__ __align__(16) float g_h[MAXN * 128];
__device__ __align__(16) float g_dis[MAXN];
__device__ __align__(16) int   g_cnt[MAXN];
__device__ __align__(16) int   g_offs[MAXN + 1];
__device__ __align__(16) int   g_cur[MAXN];
__device__ __align__(16) int   g_adj[MAXE];
__device__ __align__(16) int   g_bsum[128];
__device__ __align__(16) float g_sums[NG_GRAPHS * 64];
__device__ __align__(16) float g_gcnt[NG_GRAPHS];

// ---------------------------------------------------------------------------
// CSR build: count, scan, fill
// ---------------------------------------------------------------------------
__global__ void count_kernel(const int* __restrict__ dst, int* cnt, int E) {
    int i = blockIdx.x * blockDim.x + threadIdx.x;
    if (i < E) atomicAdd(&cnt[dst[i]], 1);
}

__global__ __launch_bounds__(SCAN_B) void scan_block_kernel(
    const int* __restrict__ cnt, int* offs, int* bsum, int N) {
    __shared__ int sh[SCAN_B];
    int t = threadIdx.x;
    int i = blockIdx.x * SCAN_B + t;
    int v = (i < N) ? cnt[i] : 0;
    sh[t] = v;
    __syncthreads();
#pragma unroll
    for (int off = 1; off < SCAN_B; off <<= 1) {
        int add = (t >= off) ? sh[t - off] : 0;
        __syncthreads();
        sh[t] += add;
        __syncthreads();
    }
    if (i < N + 1 && i <= N) { /* nothing */ }
    if (i < N) offs[i] = sh[t] - v;  // exclusive
    if (t == SCAN_B - 1) bsum[blockIdx.x] = sh[t];
}

__global__ void scan_top_kernel(int* bsum, int NB) {
    __shared__ int sh[128];
    int t = threadIdx.x;
    int v = (t < NB) ? bsum[t] : 0;
    sh[t] = v;
    __syncthreads();
#pragma unroll
    for (int off = 1; off < 128; off <<= 1) {
        int add = (t >= off) ? sh[t - off] : 0;
        __syncthreads();
        sh[t] += add;
        __syncthreads();
    }
    if (t < NB) bsum[t] = sh[t] - v;  // exclusive block offsets
}

__global__ void scan_add_kernel(int* offs, const int* __restrict__ bsum,
                                int* cur, const int* __restrict__ cnt,
                                float* dis, int N, int E) {
    int i = blockIdx.x * blockDim.x + threadIdx.x;
    if (i < N) {
        int o = offs[i] + bsum[i >> 10];
        offs[i] = o;
        cur[i] = o;
        dis[i] = rsqrtf((float)cnt[i] + 1.0f);  // +1 self loop
    }
    if (i == 0) offs[N] = E;
}

__global__ void fill_kernel(const int* __restrict__ src, const int* __restrict__ dst,
                            int* cur, int* adj, int E) {
    int i = blockIdx.x * blockDim.x + threadIdx.x;
    if (i < E) {
        int slot = atomicAdd(&cur[dst[i]], 1);
        adj[slot] = src[i];
    }
}

// ---------------------------------------------------------------------------
// layer 1: t[n] = (x[n] @ W1) * dis[n],  K=3, F=128
// ---------------------------------------------------------------------------
__global__ __launch_bounds__(256) void layer1_kernel(
    const float* __restrict__ x, const float* __restrict__ W1,
    const float* __restrict__ dis, float* __restrict__ t, int N) {
    __shared__ float ws[3 * 128];
    for (int i = threadIdx.x; i < 384; i += blockDim.x) ws[i] = W1[i];
    __syncthreads();
    int idx = blockIdx.x * blockDim.x + threadIdx.x;
    int n = idx >> 5;
    int l = idx & 31;
    if (n >= N) return;
    float x0 = x[n * 3 + 0], x1 = x[n * 3 + 1], x2 = x[n * 3 + 2];
    float d = dis[n];
    int f = l * 4;
    float4 o;
    o.x = (x0 * ws[f + 0] + x1 * ws[128 + f + 0] + x2 * ws[256 + f + 0]) * d;
    o.y = (x0 * ws[f + 1] + x1 * ws[128 + f + 1] + x2 * ws[256 + f + 1]) * d;
    o.z = (x0 * ws[f + 2] + x1 * ws[128 + f + 2] + x2 * ws[256 + f + 2]) * d;
    o.w = (x0 * ws[f + 3] + x1 * ws[128 + f + 3] + x2 * ws[256 + f + 3]) * d;
    *(float4*)(t + (size_t)n * 128 + f) = o;
}

// ---------------------------------------------------------------------------
// GEMM: out[n] = (A[n] @ W) * dis[n].  K=128 fixed, F in {64,128}.
// Tile: 128 nodes x F feats, 256 threads, 8x8 (or 4x8) register microtile.
// ---------------------------------------------------------------------------
template <int F>
__global__ __launch_bounds__(256, 2) void gemm_kernel(
    const float* __restrict__ A, const float* __restrict__ W,
    const float* __restrict__ dis, float* __restrict__ out, int N) {
    constexpr int K = 128, TN = 128, KC = 8;
    constexpr int TX = F / 8;       // threads along feats (16 or 8)
    constexpr int TY = 256 / TX;    // threads along nodes (16 or 32)
    constexpr int RY = TN / TY;     // nodes per thread (8 or 4)
    __shared__ float as[KC][TN + 8];   // A^T chunk (padded; +8 keeps float4 align)
    __shared__ float ws[KC][F];

    const int tid = threadIdx.x;
    const int n0 = blockIdx.x * TN;
    const int tx = tid % TX;
    const int ty = tid / TX;

    float acc[RY][8];
#pragma unroll
    for (int i = 0; i < RY; i++)
#pragma unroll
        for (int j = 0; j < 8; j++) acc[i][j] = 0.f;

    for (int k0 = 0; k0 < K; k0 += KC) {
        // load A chunk (transpose): 128 nodes x 8 k
        {
            int r = tid >> 1;
            int c = (tid & 1) * 4;
            int n = n0 + r;
            float4 v = make_float4(0.f, 0.f, 0.f, 0.f);
            if (n < N) v = *(const float4*)(A + (size_t)n * K + k0 + c);
            as[c + 0][r] = v.x;
            as[c + 1][r] = v.y;
            as[c + 2][r] = v.z;
            as[c + 3][r] = v.w;
        }
        // load W chunk: KC x F
        {
            constexpr int TOT = KC * F / 4;
            if (tid < TOT) {
                int rr = tid / (F / 4), cc = tid % (F / 4);
                *(float4*)&ws[rr][cc * 4] = *(const float4*)(W + (size_t)(k0 + rr) * F + cc * 4);
            }
        }
        __syncthreads();
#pragma unroll
        for (int kk = 0; kk < KC; kk++) {
            float bv[8], av[RY];
            *(float4*)&bv[0] = *(float4*)&ws[kk][tx * 8];
            *(float4*)&bv[4] = *(float4*)&ws[kk][tx * 8 + 4];
#pragma unroll
            for (int i = 0; i < RY; i += 4)
                *(float4*)&av[i] = *(float4*)&as[kk][ty * RY + i];
#pragma unroll
            for (int i = 0; i < RY; i++)
#pragma unroll
                for (int j = 0; j < 8; j++)
                    acc[i][j] = fmaf(av[i], bv[j], acc[i][j]);
        }
        __syncthreads();
    }
#pragma unroll
    for (int i = 0; i < RY; i++) {
        int n = n0 + ty * RY + i;
        if (n < N) {
            float d = dis[n];
            float4 o0 = make_float4(acc[i][0] * d, acc[i][1] * d, acc[i][2] * d, acc[i][3] * d);
            float4 o1 = make_float4(acc[i][4] * d, acc[i][5] * d, acc[i][6] * d, acc[i][7] * d);
            *(float4*)(out + (size_t)n * F + tx * 8) = o0;
            *(float4*)(out + (size_t)n * F + tx * 8 + 4) = o1;
        }
    }
}

// ---------------------------------------------------------------------------
// CSR gather + epilogue: h[d] = relu(dis[d]*(sum_{s in adj(d)} t[s] + t[d]) + b)
// One warp per dst node; lane covers F/32 floats.
// ---------------------------------------------------------------------------
template <int F>
__global__ __launch_bounds__(256) void gather_kernel(
    const int* __restrict__ offs, const int* __restrict__ adj,
    const float* __restrict__ t, const float* __restrict__ dis,
    const float* __restrict__ b, float* __restrict__ h, int N) {
    int warp = (blockIdx.x * 256 + threadIdx.x) >> 5;
    int lane = threadIdx.x & 31;
    if (warp >= N) return;
    int beg = offs[warp];
    int end = offs[warp + 1];
    float d = dis[warp];
    if constexpr (F == 128) {
        const float4* tv = (const float4*)t;
        float4 s0 = __ldg(&tv[(size_t)warp * 32 + lane]);  // self loop
        float4 s1 = make_float4(0.f, 0.f, 0.f, 0.f);
        int e = beg;
        for (; e + 2 <= end; e += 2) {
            int a0 = __ldg(&adj[e]);
            int a1 = __ldg(&adj[e + 1]);
            float4 v0 = __ldg(&tv[(size_t)a0 * 32 + lane]);
            float4 v1 = __ldg(&tv[(size_t)a1 * 32 + lane]);
            s0.x += v0.x; s0.y += v0.y; s0.z += v0.z; s0.w += v0.w;
            s1.x += v1.x; s1.y += v1.y; s1.z += v1.z; s1.w += v1.w;
        }
        if (e < end) {
            int a = __ldg(&adj[e]);
            float4 v = __ldg(&tv[(size_t)a * 32 + lane]);
            s0.x += v.x; s0.y += v.y; s0.z += v.z; s0.w += v.w;
        }
        float4 bv = __ldg(&((const float4*)b)[lane]);
        float4 o;
        o.x = fmaxf(fmaf(s0.x + s1.x, d, bv.x), 0.f);
        o.y = fmaxf(fmaf(s0.y + s1.y, d, bv.y), 0.f);
        o.z = fmaxf(fmaf(s0.z + s1.z, d, bv.z), 0.f);
        o.w = fmaxf(fmaf(s0.w + s1.w, d, bv.w), 0.f);
        ((float4*)h)[(size_t)warp * 32 + lane] = o;
    } else {
        const float2* tv = (const float2*)t;
        float2 s0 = __ldg(&tv[(size_t)warp * 32 + lane]);
        float2 s1 = make_float2(0.f, 0.f);
        int e = beg;
        for (; e + 2 <= end; e += 2) {
            int a0 = __ldg(&adj[e]);
            int a1 = __ldg(&adj[e + 1]);
            float2 v0 = __ldg(&tv[(size_t)a0 * 32 + lane]);
            float2 v1 = __ldg(&tv[(size_t)a1 * 32 + lane]);
            s0.x += v0.x; s0.y += v0.y;
            s1.x += v1.x; s1.y += v1.y;
        }
        if (e < end) {
            int a = __ldg(&adj[e]);
            float2 v = __ldg(&tv[(size_t)a * 32 + lane]);
            s0.x += v.x; s0.y += v.y;
        }
        float2 bv = __ldg(&((const float2*)b)[lane]);
        float2 o;
        o.x = fmaxf(fmaf(s0.x + s1.x, d, bv.x), 0.f);
        o.y = fmaxf(fmaf(s0.y + s1.y, d, bv.y), 0.f);
        ((float2*)h)[(size_t)warp * 32 + lane] = o;
    }
}

// ---------------------------------------------------------------------------
// pooling: batch sorted -> segmented reduction, atomic flush at boundaries
// ---------------------------------------------------------------------------
__global__ __launch_bounds__(64) void pool_kernel(
    const float* __restrict__ h, const int* __restrict__ batch,
    float* __restrict__ sums, float* __restrict__ cnt, int N) {
    int start = blockIdx.x * 256;
    int end = min(start + 256, N);
    int f = threadIdx.x;
    int g = batch[start];
    float s = 0.f, c = 0.f;
    for (int n = start; n < end; n++) {
        int bn = batch[n];
        if (bn != g) {
            atomicAdd(&sums[g * 64 + f], s);
            if (f == 0) atomicAdd(&cnt[g], c);
            s = 0.f; c = 0.f; g = bn;
        }
        s += h[(size_t)n * 64 + f];
        c += 1.f;
    }
    atomicAdd(&sums[g * 64 + f], s);
    if (f == 0) atomicAdd(&cnt[g], c);
}

__global__ void final_kernel(const float* __restrict__ sums, const float* __restrict__ cnt,
                             const float* __restrict__ Wl, const float* __restrict__ bl,
                             float* __restrict__ out) {
    int g = blockIdx.x * blockDim.x + threadIdx.x;
    if (g >= NG_GRAPHS) return;
    float c = fmaxf(cnt[g], 1.0f);
    float acc = 0.f;
#pragma unroll
    for (int f = 0; f < 64; f++) acc = fmaf(sums[g * 64 + f], Wl[f], acc);
    out[g] = acc / c + bl[0];
}

// ---------------------------------------------------------------------------
extern "C" void kernel_launch(void* const* d_in, const int* in_sizes, int n_in,
                              void* d_out, int out_size) {
    const float* x     = (const float*)d_in[0];
    const int*   ei    = (const int*)d_in[1];    // int32
    const int*   batch = (const int*)d_in[2];    // int32
    const float* W1 = (const float*)d_in[3];
    const float* b1 = (const float*)d_in[4];
    const float* W2 = (const float*)d_in[5];
    const float* b2 = (const float*)d_in[6];
    const float* W3 = (const float*)d_in[7];
    const float* b3 = (const float*)d_in[8];
    const float* Wl = (const float*)d_in[9];
    const float* bl = (const float*)d_in[10];
    float* out = (float*)d_out;

    const int N = in_sizes[0] / 3;
    const int E = in_sizes[1] / 2;
    const int* srcp = ei;
    const int* dstp = ei + E;

    float *t, *h, *dis, *sums, *gcnt;
    int *cnt, *offs, *cur, *adj, *bsum;
    cudaGetSymbolAddress((void**)&t, g_t);
    cudaGetSymbolAddress((void**)&h, g_h);
    cudaGetSymbolAddress((void**)&dis, g_dis);
    cudaGetSymbolAddress((void**)&cnt, g_cnt);
    cudaGetSymbolAddress((void**)&offs, g_offs);
    cudaGetSymbolAddress((void**)&cur, g_cur);
    cudaGetSymbolAddress((void**)&adj, g_adj);
    cudaGetSymbolAddress((void**)&bsum, g_bsum);
    cudaGetSymbolAddress((void**)&sums, g_sums);
    cudaGetSymbolAddress((void**)&gcnt, g_gcnt);

    const int nB = (N + 255) / 256;
    const int eB = (E + 255) / 256;
    const int NB_SCAN = (N + SCAN_B - 1) / SCAN_B;
    const int wB = (N * 32 + 255) / 256;      // warp-per-node grids
    const int gB = (N + 127) / 128;           // gemm grids

    // --- CSR build (once, reused for all 3 layers) ---
    cudaMemsetAsync(cnt, 0, (size_t)N * sizeof(int), 0);
    count_kernel<<<eB, 256>>>(dstp, cnt, E);
    scan_block_kernel<<<NB_SCAN, SCAN_B>>>(cnt, offs, bsum, N);
    scan_top_kernel<<<1, 128>>>(bsum, NB_SCAN);
    scan_add_kernel<<<nB, 256>>>(offs, bsum, cur, cnt, dis, N, E);
    fill_kernel<<<eB, 256>>>(srcp, dstp, cur, adj, E);

    // --- layer 1 (3 -> 128) ---
    layer1_kernel<<<wB, 256>>>(x, W1, dis, t, N);
    gather_kernel<128><<<wB, 256>>>(offs, adj, t, dis, b1, h, N);

    // --- layer 2 (128 -> 128) ---
    gemm_kernel<128><<<gB, 256>>>(h, W2, dis, t, N);
    gather_kernel<128><<<wB, 256>>>(offs, adj, t, dis, b2, h, N);

    // --- layer 3 (128 -> 64) ---
    gemm_kernel<64><<<gB, 256>>>(h, W3, dis, t, N);
    gather_kernel<64><<<wB, 256>>>(offs, adj, t, dis, b3, h, N);

    // --- pooling + final linear ---
    cudaMemsetAsync(sums, 0, NG_GRAPHS * 64 * sizeof(float), 0);
    cudaMemsetAsync(gcnt, 0, NG_GRAPHS * sizeof(float), 0);
    pool_kernel<<<(N + 255) / 256, 64>>>(h, batch, sums, gcnt, N);
    final_kernel<<<2, 256>>>(sums, gcnt, Wl, bl, out);
}